// round 15
// baseline (speedup 1.0000x reference)
#include <cuda_runtime.h>
#include <cstdint>

// x      [B=4, C=64, T=1000, F=96]  f32
// weight [F=96, 320, O=2] f32 (idx ck = c*5+k) ; bias [F=96, O=2]
// out    [B=4, O=2, T=1000, F=96]  f32
// out[b,o,t,f] = sum_{c,k} x[b,c,t-4+k,f] * w[f,ck,o] + bias[f,o]

#define FD 96
#define FP 48                     // f-pairs
#define CD 64
#define TD 1000
#define TC 5
#define TPG 5
#define NTG 2                     // t-groups per block
#define TT (NTG * TPG)            // 10 output t per block
#define NTHREADS (FP * NTG)       // 96
#define NTILES (TD / TT)          // 100
#define WROWS (TPG + TC - 1)      // 9
#define SLAB_ROWS (TT + TC - 1)   // 14 rows per c-slab (includes 4-row halo)
#define SLAB_BYTES (SLAB_ROWS * FD * 4)     // 5376
#define GROUP 2                   // c-slabs per pipeline stage
#define NGROUPS (CD / GROUP)      // 32
#define NSTAGES 4                 // 3 stages in flight
#define WSLAB_BYTES (GROUP * TC * FP * 16)  // 7680 (weights for GROUP c's)
#define STAGE_BYTES (GROUP * SLAB_BYTES + WSLAB_BYTES)  // 18432
#define DSMEM_BYTES (NSTAGES * STAGE_BYTES)             // 73728

typedef unsigned long long u64;

// Warp-coalesced transposed weights: g_wt[(ck*FP + fp)*2 + o]
//   = (w[2fp,ck,o], w[2fp+1,ck,o]) packed u64 (f-pair in the two f32x2 lanes).
// Contiguous per ck-range -> each stage's weights are ONE bulk copy.
__device__ __align__(16) u64 g_wt[CD * TC * FP * 2];   // 245 KB
__device__ u64 g_bt[FP * 2];                           // bias pairs

__device__ __forceinline__ u64 pack2(float lo, float hi) {
    u64 r; asm("mov.b64 %0, {%1, %2};" : "=l"(r) : "f"(lo), "f"(hi)); return r;
}
__device__ __forceinline__ void ffma2(u64& d, u64 a, u64 b) {
    asm("fma.rn.f32x2 %0, %1, %2, %0;" : "+l"(d) : "l"(a), "l"(b));
}
__device__ __forceinline__ void mbar_init(uint32_t bar, uint32_t cnt) {
    asm volatile("mbarrier.init.shared.b64 [%0], %1;" :: "r"(bar), "r"(cnt) : "memory");
}
__device__ __forceinline__ void mbar_expect_tx(uint32_t bar, uint32_t tx) {
    asm volatile("mbarrier.arrive.expect_tx.shared.b64 _, [%0], %1;"
                 :: "r"(bar), "r"(tx) : "memory");
}
__device__ __forceinline__ void mbar_wait(uint32_t bar, uint32_t parity) {
    asm volatile(
        "{\n\t.reg .pred P;\n\t"
        "WAIT_%=:\n\t"
        "mbarrier.try_wait.parity.acquire.cta.shared::cta.b64 P, [%0], %1, 0x989680;\n\t"
        "@!P bra WAIT_%=;\n\t"
        "}" :: "r"(bar), "r"(parity) : "memory");
}
__device__ __forceinline__ void bulk_ld(uint32_t dst, const void* src,
                                        uint32_t bytes, uint32_t bar) {
    asm volatile("cp.async.bulk.shared::cta.global.mbarrier::complete_tx::bytes "
                 "[%0], [%1], %2, [%3];"
                 :: "r"(dst), "l"(src), "r"(bytes), "r"(bar) : "memory");
}

__global__ void transpose_w(const float* __restrict__ w, const float* __restrict__ b) {
    int i = blockIdx.x * blockDim.x + threadIdx.x;       // over CD*TC*FP*2 = 30720
    if (i < CD * TC * FP * 2) {
        int ck  = i / (FP * 2);
        int rem = i % (FP * 2);
        int fp  = rem >> 1, o = rem & 1;
        int f   = 2 * fp;
        g_wt[i] = pack2(w[(f * (CD * TC) + ck) * 2 + o],
                        w[((f + 1) * (CD * TC) + ck) * 2 + o]);
    }
    if (i < FP * 2) {
        int fp = i >> 1, o = i & 1;
        g_bt[i] = pack2(b[(2 * fp) * 2 + o], b[(2 * fp + 1) * 2 + o]);
    }
}

__global__ __launch_bounds__(NTHREADS)
void decoder_out_kernel(const float* __restrict__ x, float* __restrict__ out)
{
    extern __shared__ __align__(16) char smem[];   // NSTAGES stages of x-slabs + w-slab
    __shared__ __align__(8) u64 mbar[NSTAGES];

    const int tid  = threadIdx.x;
    const int fp   = tid % FP;               // f-pair lane
    const int tg   = tid / FP;               // t-group 0/1
    const int tile = blockIdx.x;
    const int bb   = blockIdx.y;
    const int t0   = tile * TT;
    const int tstart = t0 + tg * TPG;

    // Tile 0: rows 0..3 of every x-slab are t<0 -> zero once; bulk never writes them.
    const int      nskip      = (tile == 0) ? (TC - 1) : 0;
    const uint32_t slab_off   = (uint32_t)(nskip * FD * 4);
    const uint32_t bulk_bytes = (uint32_t)((SLAB_ROWS - nskip) * FD * 4);
    const char* __restrict__ xsrc0 = (const char*)x +
        ((size_t)bb * CD * TD + (size_t)(t0 - (TC - 1) + nskip)) * (FD * 4);

    const uint32_t smem_base = (uint32_t)__cvta_generic_to_shared(&smem[0]);
    const uint32_t bar_base  = (uint32_t)__cvta_generic_to_shared(&mbar[0]);

    if (tile == 0) {
        for (int i = tid; i < (TC - 1) * FD; i += NTHREADS) {
#pragma unroll
            for (int s = 0; s < NSTAGES; ++s)
#pragma unroll
                for (int ci = 0; ci < GROUP; ++ci)
                    reinterpret_cast<float*>(
                        smem + s * STAGE_BYTES + ci * SLAB_BYTES)[i] = 0.f;
        }
    }
    if (tid == 0) {
#pragma unroll
        for (int s = 0; s < NSTAGES; ++s) mbar_init(bar_base + s * 8, 1);
    }
    __syncthreads();
    asm volatile("fence.proxy.async.shared::cta;" ::: "memory");

    // producer: one thread issues GROUP x-slabs + 1 weight slab per stage
    auto issue_group = [&](int g) {
        const int stage = g % NSTAGES;
        const uint32_t bar = bar_base + stage * 8;
        const uint32_t sb  = smem_base + (uint32_t)stage * STAGE_BYTES;
        mbar_expect_tx(bar, GROUP * bulk_bytes + WSLAB_BYTES);
#pragma unroll
        for (int ci = 0; ci < GROUP; ++ci) {
            const int c = g * GROUP + ci;
            bulk_ld(sb + (uint32_t)ci * SLAB_BYTES + slab_off,
                    xsrc0 + (size_t)c * (TD * FD * 4), bulk_bytes, bar);
        }
        bulk_ld(sb + GROUP * SLAB_BYTES,
                (const char*)g_wt + (size_t)g * WSLAB_BYTES, WSLAB_BYTES, bar);
    };
    if (tid == 0) { issue_group(0); issue_group(1); issue_group(2); }

    // accumulators: acc[t][o], lanes = (f, f+1); init with bias
    u64 acc[TPG][2];
    {
        const u64 b0 = g_bt[fp * 2 + 0], b1 = g_bt[fp * 2 + 1];
#pragma unroll
        for (int t = 0; t < TPG; ++t) { acc[t][0] = b0; acc[t][1] = b1; }
    }

    for (int g = 0; g < NGROUPS; ++g) {
        const int stage = g % NSTAGES;
        mbar_wait(bar_base + stage * 8, (g / NSTAGES) & 1);

        // re-issue at the TOP: stage (g-1)%NSTAGES was drained at end of g-1.
        if (g + (NSTAGES - 1) < NGROUPS && tid == 0) issue_group(g + (NSTAGES - 1));

        const char* sb = smem + stage * STAGE_BYTES;
#pragma unroll
        for (int ci = 0; ci < GROUP; ++ci) {
            // window rows (lanes = consecutive fp -> conflict-free LDS.64)
            const u64* __restrict__ xq = reinterpret_cast<const u64*>(
                sb + ci * SLAB_BYTES + (tg * TPG) * (FD * 4)) + fp;
            u64 xv[WROWS];
#pragma unroll
            for (int r = 0; r < WROWS; ++r) xv[r] = xq[r * FP];

            // weights from smem (conflict-free LDS.128)
            const ulonglong2* __restrict__ wq = reinterpret_cast<const ulonglong2*>(
                sb + GROUP * SLAB_BYTES) + ci * (TC * FP) + fp;
#pragma unroll
            for (int k = 0; k < TC; ++k) {
                const ulonglong2 wv = wq[k * FP];
#pragma unroll
                for (int t = 0; t < TPG; ++t) {
                    ffma2(acc[t][0], xv[t + k], wv.x);
                    ffma2(acc[t][1], xv[t + k], wv.y);
                }
            }
        }
        __syncthreads();   // all warps done reading stage g before it is re-filled
    }

    // out[b][o][t][f]: store float2 at f = 2*fp
    const size_t os = (size_t)TD * FD;
    char* op = (char*)out + ((size_t)bb * 2 * os + (size_t)tstart * FD + 2 * fp) * 4;
#pragma unroll
    for (int t = 0; t < TPG; ++t) {
        *reinterpret_cast<u64*>(op + (size_t)t * FD * 4)        = acc[t][0]; // o=0
        *reinterpret_cast<u64*>(op + (os + (size_t)t * FD) * 4) = acc[t][1]; // o=1
    }
}

extern "C" void kernel_launch(void* const* d_in, const int* in_sizes, int n_in,
                              void* d_out, int out_size)
{
    const float* x    = (const float*)d_in[0];
    const float* w    = (const float*)d_in[1];
    const float* bias = (const float*)d_in[2];
    float* out        = (float*)d_out;

    // 72 KB dynamic smem ring; idempotent, capture-safe
    cudaFuncSetAttribute(decoder_out_kernel,
                         cudaFuncAttributeMaxDynamicSharedMemorySize, DSMEM_BYTES);

    transpose_w<<<(CD * TC * FP * 2 + 127) / 128, 128>>>(w, bias);
    dim3 grid(NTILES, 4);   // 100 t-tiles x B=4 = 400 blocks x 96 threads
    decoder_out_kernel<<<grid, NTHREADS, DSMEM_BYTES>>>(x, out);
}

// round 16
// speedup vs baseline: 1.0011x; 1.0011x over previous
#include <cuda_runtime.h>
#include <cstdint>

// x      [B=4, C=64, T=1000, F=96]  f32
// weight [F=96, 320, O=2] f32 (idx ck = c*5+k) ; bias [F=96, O=2]
// out    [B=4, O=2, T=1000, F=96]  f32
// out[b,o,t,f] = sum_{c,k} x[b,c,t-4+k,f] * w[f,ck,o] + bias[f,o]

#define FD 96
#define FP 48                     // f-pairs
#define CD 64
#define TD 1000
#define TC 5
#define CK (CD * TC)              // 320
#define TPG 5
#define NTG 2                     // t-groups per block
#define TT (NTG * TPG)            // 10 output t per block
#define NTHREADS (FP * NTG)       // 96
#define NTILES (TD / TT)          // 100
#define WROWS (TPG + TC - 1)      // 9
#define SLAB_ROWS (TT + TC - 1)   // 14 rows per c-slab (includes 4-row halo)
#define SLAB_BYTES (SLAB_ROWS * FD * 4)     // 5376
#define GROUP 2                   // c-slabs per pipeline stage
#define NGROUPS (CD / GROUP)      // 32
#define NSTAGES 4                 // 3 stages in flight
#define WSLAB_BYTES (GROUP * TC * FP * 16)  // 7680 (weights for GROUP c's)
#define STAGE_BYTES (GROUP * SLAB_BYTES + WSLAB_BYTES)  // 18432
#define DSMEM_BYTES (NSTAGES * STAGE_BYTES)             // 73728

typedef unsigned long long u64;

// Warp-coalesced transposed weights: g_wt[(ck*FP + fp)*2 + o]
//   = (w[2fp,ck,o], w[2fp+1,ck,o]) packed u64 (f-pair in the two f32x2 lanes).
// Contiguous per ck-range -> each stage's weights are ONE bulk copy.
__device__ __align__(16) u64 g_wt[CK * FP * 2];        // 245 KB
__device__ u64 g_bt[FP * 2];                           // bias pairs

__device__ __forceinline__ u64 pack2(float lo, float hi) {
    u64 r; asm("mov.b64 %0, {%1, %2};" : "=l"(r) : "f"(lo), "f"(hi)); return r;
}
__device__ __forceinline__ void ffma2(u64& d, u64 a, u64 b) {
    asm("fma.rn.f32x2 %0, %1, %2, %0;" : "+l"(d) : "l"(a), "l"(b));
}
__device__ __forceinline__ void mbar_init(uint32_t bar, uint32_t cnt) {
    asm volatile("mbarrier.init.shared.b64 [%0], %1;" :: "r"(bar), "r"(cnt) : "memory");
}
__device__ __forceinline__ void mbar_expect_tx(uint32_t bar, uint32_t tx) {
    asm volatile("mbarrier.arrive.expect_tx.shared.b64 _, [%0], %1;"
                 :: "r"(bar), "r"(tx) : "memory");
}
__device__ __forceinline__ void mbar_wait(uint32_t bar, uint32_t parity) {
    asm volatile(
        "{\n\t.reg .pred P;\n\t"
        "WAIT_%=:\n\t"
        "mbarrier.try_wait.parity.acquire.cta.shared::cta.b64 P, [%0], %1, 0x989680;\n\t"
        "@!P bra WAIT_%=;\n\t"
        "}" :: "r"(bar), "r"(parity) : "memory");
}
__device__ __forceinline__ void bulk_ld(uint32_t dst, const void* src,
                                        uint32_t bytes, uint32_t bar) {
    asm volatile("cp.async.bulk.shared::cta.global.mbarrier::complete_tx::bytes "
                 "[%0], [%1], %2, [%3];"
                 :: "r"(dst), "l"(src), "r"(bytes), "r"(bar) : "memory");
}

// Coalesced weight repack: thread j <-> (fp, ck). Reads the two o-pair u64s
// of f=2fp and f=2fp+1 (consecutive j -> consecutive ck -> fully coalesced
// LDG.64), lane-swaps in registers, scatter-stores the two output u64s.
__global__ __launch_bounds__(128)
void transpose_w(const float* __restrict__ w, const float* __restrict__ b) {
    const int j = blockIdx.x * blockDim.x + threadIdx.x;   // over FP*CK = 15360
    if (j < FP * CK) {
        const int fp = j / CK;
        const int ck = j % CK;
        const float2* __restrict__ w2 = reinterpret_cast<const float2*>(w);
        const float2 a = w2[(2 * fp)     * CK + ck];   // (w[2fp ,ck,0], w[2fp ,ck,1])
        const float2 c = w2[(2 * fp + 1) * CK + ck];   // (w[2fp+1,ck,0], w[2fp+1,ck,1])
        g_wt[(ck * FP + fp) * 2 + 0] = pack2(a.x, c.x); // o = 0
        g_wt[(ck * FP + fp) * 2 + 1] = pack2(a.y, c.y); // o = 1
    }
    if (j < FP) {
        const float2* __restrict__ b2 = reinterpret_cast<const float2*>(b);
        const float2 a = b2[2 * j];
        const float2 c = b2[2 * j + 1];
        g_bt[j * 2 + 0] = pack2(a.x, c.x);
        g_bt[j * 2 + 1] = pack2(a.y, c.y);
    }
}

__global__ __launch_bounds__(NTHREADS)
void decoder_out_kernel(const float* __restrict__ x, float* __restrict__ out)
{
    extern __shared__ __align__(16) char smem[];   // NSTAGES stages of x-slabs + w-slab
    __shared__ __align__(8) u64 mbar[NSTAGES];

    const int tid  = threadIdx.x;
    const int fp   = tid % FP;               // f-pair lane
    const int tg   = tid / FP;               // t-group 0/1
    const int tile = blockIdx.x;
    const int bb   = blockIdx.y;
    const int t0   = tile * TT;
    const int tstart = t0 + tg * TPG;

    // Tile 0: rows 0..3 of every x-slab are t<0 -> zero once; bulk never writes them.
    const int      nskip      = (tile == 0) ? (TC - 1) : 0;
    const uint32_t slab_off   = (uint32_t)(nskip * FD * 4);
    const uint32_t bulk_bytes = (uint32_t)((SLAB_ROWS - nskip) * FD * 4);
    const char* __restrict__ xsrc0 = (const char*)x +
        ((size_t)bb * CD * TD + (size_t)(t0 - (TC - 1) + nskip)) * (FD * 4);

    const uint32_t smem_base = (uint32_t)__cvta_generic_to_shared(&smem[0]);
    const uint32_t bar_base  = (uint32_t)__cvta_generic_to_shared(&mbar[0]);

    if (tile == 0) {
        for (int i = tid; i < (TC - 1) * FD; i += NTHREADS) {
#pragma unroll
            for (int s = 0; s < NSTAGES; ++s)
#pragma unroll
                for (int ci = 0; ci < GROUP; ++ci)
                    reinterpret_cast<float*>(
                        smem + s * STAGE_BYTES + ci * SLAB_BYTES)[i] = 0.f;
        }
    }
    if (tid == 0) {
#pragma unroll
        for (int s = 0; s < NSTAGES; ++s) mbar_init(bar_base + s * 8, 1);
    }
    __syncthreads();
    asm volatile("fence.proxy.async.shared::cta;" ::: "memory");

    // producer: one thread issues GROUP x-slabs + 1 weight slab per stage
    auto issue_group = [&](int g) {
        const int stage = g % NSTAGES;
        const uint32_t bar = bar_base + stage * 8;
        const uint32_t sb  = smem_base + (uint32_t)stage * STAGE_BYTES;
        mbar_expect_tx(bar, GROUP * bulk_bytes + WSLAB_BYTES);
#pragma unroll
        for (int ci = 0; ci < GROUP; ++ci) {
            const int c = g * GROUP + ci;
            bulk_ld(sb + (uint32_t)ci * SLAB_BYTES + slab_off,
                    xsrc0 + (size_t)c * (TD * FD * 4), bulk_bytes, bar);
        }
        bulk_ld(sb + GROUP * SLAB_BYTES,
                (const char*)g_wt + (size_t)g * WSLAB_BYTES, WSLAB_BYTES, bar);
    };
    if (tid == 0) { issue_group(0); issue_group(1); issue_group(2); }

    // accumulators: acc[t][o], lanes = (f, f+1); init with bias
    u64 acc[TPG][2];
    {
        const u64 b0 = g_bt[fp * 2 + 0], b1 = g_bt[fp * 2 + 1];
#pragma unroll
        for (int t = 0; t < TPG; ++t) { acc[t][0] = b0; acc[t][1] = b1; }
    }

    for (int g = 0; g < NGROUPS; ++g) {
        const int stage = g % NSTAGES;
        mbar_wait(bar_base + stage * 8, (g / NSTAGES) & 1);

        // re-issue at the TOP: stage (g-1)%NSTAGES was drained at end of g-1.
        if (g + (NSTAGES - 1) < NGROUPS && tid == 0) issue_group(g + (NSTAGES - 1));

        const char* sb = smem + stage * STAGE_BYTES;
#pragma unroll
        for (int ci = 0; ci < GROUP; ++ci) {
            // window rows (lanes = consecutive fp -> conflict-free LDS.64)
            const u64* __restrict__ xq = reinterpret_cast<const u64*>(
                sb + ci * SLAB_BYTES + (tg * TPG) * (FD * 4)) + fp;
            u64 xv[WROWS];
#pragma unroll
            for (int r = 0; r < WROWS; ++r) xv[r] = xq[r * FP];

            // weights from smem (conflict-free LDS.128)
            const ulonglong2* __restrict__ wq = reinterpret_cast<const ulonglong2*>(
                sb + GROUP * SLAB_BYTES) + ci * (TC * FP) + fp;
#pragma unroll
            for (int k = 0; k < TC; ++k) {
                const ulonglong2 wv = wq[k * FP];
#pragma unroll
                for (int t = 0; t < TPG; ++t) {
                    ffma2(acc[t][0], xv[t + k], wv.x);
                    ffma2(acc[t][1], xv[t + k], wv.y);
                }
            }
        }
        __syncthreads();   // all warps done reading stage g before it is re-filled
    }

    // out[b][o][t][f]: store float2 at f = 2*fp
    const size_t os = (size_t)TD * FD;
    char* op = (char*)out + ((size_t)bb * 2 * os + (size_t)tstart * FD + 2 * fp) * 4;
#pragma unroll
    for (int t = 0; t < TPG; ++t) {
        *reinterpret_cast<u64*>(op + (size_t)t * FD * 4)        = acc[t][0]; // o=0
        *reinterpret_cast<u64*>(op + (os + (size_t)t * FD) * 4) = acc[t][1]; // o=1
    }
}

extern "C" void kernel_launch(void* const* d_in, const int* in_sizes, int n_in,
                              void* d_out, int out_size)
{
    const float* x    = (const float*)d_in[0];
    const float* w    = (const float*)d_in[1];
    const float* bias = (const float*)d_in[2];
    float* out        = (float*)d_out;

    // 72 KB dynamic smem ring; idempotent, capture-safe
    cudaFuncSetAttribute(decoder_out_kernel,
                         cudaFuncAttributeMaxDynamicSharedMemorySize, DSMEM_BYTES);

    transpose_w<<<(FP * CK + 127) / 128, 128>>>(w, bias);
    dim3 grid(NTILES, 4);   // 100 t-tiles x B=4 = 400 blocks x 96 threads
    decoder_out_kernel<<<grid, NTHREADS, DSMEM_BYTES>>>(x, out);
}

// round 17
// speedup vs baseline: 1.0781x; 1.0769x over previous
#include <cuda_runtime.h>
#include <cstdint>

// x      [B=4, C=64, T=1000, F=96]  f32
// weight [F=96, 320, O=2] f32 (idx ck = c*5+k) ; bias [F=96, O=2]
// out    [B=4, O=2, T=1000, F=96]  f32
// out[b,o,t,f] = sum_{c,k} x[b,c,t-4+k,f] * w[f,ck,o] + bias[f,o]

#define FD 96
#define FP 48                     // f-pairs
#define CD 64
#define TD 1000
#define TC 5
#define CK (CD * TC)              // 320
#define TPG 5
#define NTG 2                     // t-groups
#define TT (NTG * TPG)            // 10 output t per block
#define NCG 2                     // c-groups per block (C split 2x32)
#define NTHREADS (FP * NTG * NCG) // 192
#define NTILES (TD / TT)          // 100
#define WROWS (TPG + TC - 1)      // 9
#define SLAB_ROWS (TT + TC - 1)   // 14 rows per c-slab (includes 4-row halo)
#define SLAB_BYTES (SLAB_ROWS * FD * 4)     // 5376
#define GROUP 2                   // c-slabs per pipeline stage (one per c-group)
#define NGROUPS (CD / GROUP)      // 32
#define NSTAGES 4                 // 3 stages in flight
#define WSLAB_BYTES (GROUP * TC * FP * 16)  // 7680 (weights for GROUP c's)
#define STAGE_BYTES (GROUP * SLAB_BYTES + WSLAB_BYTES)  // 18432
#define DSMEM_BYTES (NSTAGES * STAGE_BYTES)             // 73728

typedef unsigned long long u64;

// Warp-coalesced transposed weights: g_wt[(ck*FP + fp)*2 + o]
//   = (w[2fp,ck,o], w[2fp+1,ck,o]) packed u64 (f-pair in the two f32x2 lanes).
// Contiguous per ck-range -> each stage's weights are ONE bulk copy.
__device__ __align__(16) u64 g_wt[CK * FP * 2];        // 245 KB
__device__ u64 g_bt[FP * 2];                           // bias pairs

__device__ __forceinline__ u64 pack2(float lo, float hi) {
    u64 r; asm("mov.b64 %0, {%1, %2};" : "=l"(r) : "f"(lo), "f"(hi)); return r;
}
__device__ __forceinline__ void ffma2(u64& d, u64 a, u64 b) {
    asm("fma.rn.f32x2 %0, %1, %2, %0;" : "+l"(d) : "l"(a), "l"(b));
}
__device__ __forceinline__ void fadd2(u64& d, u64 a) {
    asm("add.rn.f32x2 %0, %0, %1;" : "+l"(d) : "l"(a));
}
__device__ __forceinline__ void mbar_init(uint32_t bar, uint32_t cnt) {
    asm volatile("mbarrier.init.shared.b64 [%0], %1;" :: "r"(bar), "r"(cnt) : "memory");
}
__device__ __forceinline__ void mbar_expect_tx(uint32_t bar, uint32_t tx) {
    asm volatile("mbarrier.arrive.expect_tx.shared.b64 _, [%0], %1;"
                 :: "r"(bar), "r"(tx) : "memory");
}
__device__ __forceinline__ void mbar_wait(uint32_t bar, uint32_t parity) {
    asm volatile(
        "{\n\t.reg .pred P;\n\t"
        "WAIT_%=:\n\t"
        "mbarrier.try_wait.parity.acquire.cta.shared::cta.b64 P, [%0], %1, 0x989680;\n\t"
        "@!P bra WAIT_%=;\n\t"
        "}" :: "r"(bar), "r"(parity) : "memory");
}
__device__ __forceinline__ void bulk_ld(uint32_t dst, const void* src,
                                        uint32_t bytes, uint32_t bar) {
    asm volatile("cp.async.bulk.shared::cta.global.mbarrier::complete_tx::bytes "
                 "[%0], [%1], %2, [%3];"
                 :: "r"(dst), "l"(src), "r"(bytes), "r"(bar) : "memory");
}

// Coalesced weight repack: thread j <-> (fp, ck). Consecutive j -> consecutive ck
// -> fully coalesced LDG.64; lane-swap in registers; scatter-store outputs.
__global__ __launch_bounds__(128)
void transpose_w(const float* __restrict__ w, const float* __restrict__ b) {
    const int j = blockIdx.x * blockDim.x + threadIdx.x;   // over FP*CK = 15360
    if (j < FP * CK) {
        const int fp = j / CK;
        const int ck = j % CK;
        const float2* __restrict__ w2 = reinterpret_cast<const float2*>(w);
        const float2 a = w2[(2 * fp)     * CK + ck];
        const float2 c = w2[(2 * fp + 1) * CK + ck];
        g_wt[(ck * FP + fp) * 2 + 0] = pack2(a.x, c.x); // o = 0
        g_wt[(ck * FP + fp) * 2 + 1] = pack2(a.y, c.y); // o = 1
    }
    if (j < FP) {
        const float2* __restrict__ b2 = reinterpret_cast<const float2*>(b);
        const float2 a = b2[2 * j];
        const float2 c = b2[2 * j + 1];
        g_bt[j * 2 + 0] = pack2(a.x, c.x);
        g_bt[j * 2 + 1] = pack2(a.y, c.y);
    }
}

__global__ __launch_bounds__(NTHREADS)
void decoder_out_kernel(const float* __restrict__ x, float* __restrict__ out)
{
    extern __shared__ __align__(16) char smem[];   // NSTAGES stages of x-slabs + w-slab
    __shared__ __align__(8) u64 mbar[NSTAGES];

    const int tid  = threadIdx.x;
    const int fp   = tid % FP;               // f-pair lane
    const int tg   = (tid / FP) % NTG;       // t-group 0/1
    const int cg   = tid / (FP * NTG);       // c-group 0/1
    const int tile = blockIdx.x;
    const int bb   = blockIdx.y;
    const int t0   = tile * TT;
    const int tstart = t0 + tg * TPG;

    // Tile 0: rows 0..3 of every x-slab are t<0 -> zero once; bulk never writes them.
    const int      nskip      = (tile == 0) ? (TC - 1) : 0;
    const uint32_t slab_off   = (uint32_t)(nskip * FD * 4);
    const uint32_t bulk_bytes = (uint32_t)((SLAB_ROWS - nskip) * FD * 4);
    const char* __restrict__ xsrc0 = (const char*)x +
        ((size_t)bb * CD * TD + (size_t)(t0 - (TC - 1) + nskip)) * (FD * 4);

    const uint32_t smem_base = (uint32_t)__cvta_generic_to_shared(&smem[0]);
    const uint32_t bar_base  = (uint32_t)__cvta_generic_to_shared(&mbar[0]);

    if (tile == 0) {
        for (int i = tid; i < (TC - 1) * FD; i += NTHREADS) {
#pragma unroll
            for (int s = 0; s < NSTAGES; ++s)
#pragma unroll
                for (int ci = 0; ci < GROUP; ++ci)
                    reinterpret_cast<float*>(
                        smem + s * STAGE_BYTES + ci * SLAB_BYTES)[i] = 0.f;
        }
    }
    if (tid == 0) {
#pragma unroll
        for (int s = 0; s < NSTAGES; ++s) mbar_init(bar_base + s * 8, 1);
    }
    __syncthreads();
    asm volatile("fence.proxy.async.shared::cta;" ::: "memory");

    // producer: one thread issues GROUP x-slabs + 1 weight slab per stage
    auto issue_group = [&](int g) {
        const int stage = g % NSTAGES;
        const uint32_t bar = bar_base + stage * 8;
        const uint32_t sb  = smem_base + (uint32_t)stage * STAGE_BYTES;
        mbar_expect_tx(bar, GROUP * bulk_bytes + WSLAB_BYTES);
#pragma unroll
        for (int ci = 0; ci < GROUP; ++ci) {
            const int c = g * GROUP + ci;
            bulk_ld(sb + (uint32_t)ci * SLAB_BYTES + slab_off,
                    xsrc0 + (size_t)c * (TD * FD * 4), bulk_bytes, bar);
        }
        bulk_ld(sb + GROUP * SLAB_BYTES,
                (const char*)g_wt + (size_t)g * WSLAB_BYTES, WSLAB_BYTES, bar);
    };
    if (tid == 0) { issue_group(0); issue_group(1); issue_group(2); }

    // accumulators: acc[t][o], lanes = (f, f+1); c-group 0 carries the bias
    u64 acc[TPG][2];
    {
        u64 b0 = 0ull, b1 = 0ull;
        if (cg == 0) { b0 = g_bt[fp * 2 + 0]; b1 = g_bt[fp * 2 + 1]; }
#pragma unroll
        for (int t = 0; t < TPG; ++t) { acc[t][0] = b0; acc[t][1] = b1; }
    }

    for (int g = 0; g < NGROUPS; ++g) {
        const int stage = g % NSTAGES;
        mbar_wait(bar_base + stage * 8, (g / NSTAGES) & 1);

        // re-issue at the TOP: stage (g-1)%NSTAGES was drained at end of g-1.
        if (g + (NSTAGES - 1) < NGROUPS && tid == 0) issue_group(g + (NSTAGES - 1));

        const char* sb = smem + stage * STAGE_BYTES;
        {
            // this c-group consumes slab ci = cg only (c = g*GROUP + cg)
            const u64* __restrict__ xq = reinterpret_cast<const u64*>(
                sb + cg * SLAB_BYTES + (tg * TPG) * (FD * 4)) + fp;
            u64 xv[WROWS];
#pragma unroll
            for (int r = 0; r < WROWS; ++r) xv[r] = xq[r * FP];

            const ulonglong2* __restrict__ wq = reinterpret_cast<const ulonglong2*>(
                sb + GROUP * SLAB_BYTES) + cg * (TC * FP) + fp;
#pragma unroll
            for (int k = 0; k < TC; ++k) {
                const ulonglong2 wv = wq[k * FP];
#pragma unroll
                for (int t = 0; t < TPG; ++t) {
                    ffma2(acc[t][0], xv[t + k], wv.x);
                    ffma2(acc[t][1], xv[t + k], wv.y);
                }
            }
        }
        __syncthreads();   // both c-groups done reading stage g before re-fill
    }

    // cross-c-group reduction: reuse ring smem (all stages drained).
    // part[((tg*TPG + t)*2 + o)*FP + fp] -> lanes consecutive fp, conflict-free.
    u64* part = reinterpret_cast<u64*>(smem);
    if (cg == 1) {
#pragma unroll
        for (int t = 0; t < TPG; ++t) {
            part[(((tg * TPG + t) * 2 + 0) * FP) + fp] = acc[t][0];
            part[(((tg * TPG + t) * 2 + 1) * FP) + fp] = acc[t][1];
        }
    }
    __syncthreads();
    if (cg == 0) {
        const size_t os = (size_t)TD * FD;
        char* op = (char*)out + ((size_t)bb * 2 * os + (size_t)tstart * FD + 2 * fp) * 4;
#pragma unroll
        for (int t = 0; t < TPG; ++t) {
            fadd2(acc[t][0], part[(((tg * TPG + t) * 2 + 0) * FP) + fp]);
            fadd2(acc[t][1], part[(((tg * TPG + t) * 2 + 1) * FP) + fp]);
            *reinterpret_cast<u64*>(op + (size_t)t * FD * 4)        = acc[t][0]; // o=0
            *reinterpret_cast<u64*>(op + (os + (size_t)t * FD) * 4) = acc[t][1]; // o=1
        }
    }
}

extern "C" void kernel_launch(void* const* d_in, const int* in_sizes, int n_in,
                              void* d_out, int out_size)
{
    const float* x    = (const float*)d_in[0];
    const float* w    = (const float*)d_in[1];
    const float* bias = (const float*)d_in[2];
    float* out        = (float*)d_out;

    // 72 KB dynamic smem ring; idempotent, capture-safe
    cudaFuncSetAttribute(decoder_out_kernel,
                         cudaFuncAttributeMaxDynamicSharedMemorySize, DSMEM_BYTES);

    transpose_w<<<(FP * CK + 127) / 128, 128>>>(w, bias);
    dim3 grid(NTILES, 4);   // 100 t-tiles x B=4 = 400 blocks x 192 threads
    decoder_out_kernel<<<grid, NTHREADS, DSMEM_BYTES>>>(x, out);
}